// round 1
// baseline (speedup 1.0000x reference)
#include <cuda_runtime.h>
#include <cstdint>
#include <cstddef>

// Problem constants
#define NVOBJ 2048
#define KK    8
#define LL    10
#define DD    300
#define FF    512
#define NOBJ  4096
#define TM    3
#define BSEQ  (NVOBJ*KK)        // 16384
#define BLTOT (BSEQ*LL)         // 163840
#define G3D   (3*DD)            // 900
#define ZDIM  (4*DD)            // 1200
#define CAT2  (DD+FF)           // 812

// ---------------- scratch (device globals; no allocation) ----------------
__device__ float g_xg[(size_t)BLTOT*G3D];   // 590 MB: per-timestep input gates
__device__ float g_xrev[(size_t)BLTOT*DD];  // 197 MB: reversed sequences
__device__ float g_hg[(size_t)BSEQ*G3D];
__device__ float g_h[BSEQ*DD];
__device__ float g_facts[BSEQ*DD];
__device__ float g_feats[NVOBJ*FF];
__device__ float g_q[NVOBJ*DD];
__device__ float g_m[NVOBJ*DD];
__device__ float g_z[(size_t)BSEQ*ZDIM];
__device__ float g_h1[(size_t)BSEQ*FF];
__device__ float g_gate[BSEQ];
__device__ float g_fWr[BSEQ*DD];
__device__ float g_fWh[BSEQ*DD];
__device__ float g_hUr[NVOBJ*DD];
__device__ float g_hUh[NVOBJ*DD];
__device__ float g_attn[NVOBJ*DD];
__device__ float g_cat[NVOBJ*G3D];
__device__ float g_cat2[NVOBJ*CAT2];
__device__ float g_upd[NVOBJ*FF];

__device__ __forceinline__ float sigm(float x) { return 1.f / (1.f + expf(-x)); }

// ---------------- generic NT GEMM: C = act(A(M,K) @ B(N,K)^T + bias) -----
// act: 0=none, 1=tanh, 2=relu. Requires K % 4 == 0.
__global__ __launch_bounds__(256) void gemm_nt(
    const float* __restrict__ A, const float* __restrict__ B,
    const float* __restrict__ bias, float* __restrict__ C,
    int M, int N, int K, int act)
{
    const int BM = 128, BN = 64, BK = 16;
    __shared__ float As[BK][BM];
    __shared__ float Bs[BK][BN + 4];

    int bm = blockIdx.y * BM;
    int bn = blockIdx.x * BN;
    int tid = threadIdx.x;
    int tx = tid & 15;   // n: 16 x 4 cols
    int ty = tid >> 4;   // m: 16 x 8 rows

    float acc[8][4];
    #pragma unroll
    for (int i = 0; i < 8; i++)
        #pragma unroll
        for (int j = 0; j < 4; j++) acc[i][j] = 0.f;

    for (int k0 = 0; k0 < K; k0 += BK) {
        // A tile: 128x16 = 512 float4, 2 per thread
        #pragma unroll
        for (int i = 0; i < 2; ++i) {
            int f = tid + i * 256;
            int m = f >> 2;
            int kq = (f & 3) * 4;
            int gm = bm + m, gk = k0 + kq;
            float4 v = make_float4(0.f, 0.f, 0.f, 0.f);
            if (gm < M && gk < K)
                v = *reinterpret_cast<const float4*>(A + (size_t)gm * K + gk);
            As[kq + 0][m] = v.x; As[kq + 1][m] = v.y;
            As[kq + 2][m] = v.z; As[kq + 3][m] = v.w;
        }
        // B tile: 64x16 = 256 float4, 1 per thread
        {
            int n = tid >> 2;
            int kq = (tid & 3) * 4;
            int gn = bn + n, gk = k0 + kq;
            float4 v = make_float4(0.f, 0.f, 0.f, 0.f);
            if (gn < N && gk < K)
                v = *reinterpret_cast<const float4*>(B + (size_t)gn * K + gk);
            Bs[kq + 0][n] = v.x; Bs[kq + 1][n] = v.y;
            Bs[kq + 2][n] = v.z; Bs[kq + 3][n] = v.w;
        }
        __syncthreads();
        #pragma unroll
        for (int kk = 0; kk < BK; ++kk) {
            float a[8], b[4];
            #pragma unroll
            for (int i = 0; i < 8; i++) a[i] = As[kk][ty * 8 + i];
            #pragma unroll
            for (int j = 0; j < 4; j++) b[j] = Bs[kk][tx * 4 + j];
            #pragma unroll
            for (int i = 0; i < 8; i++)
                #pragma unroll
                for (int j = 0; j < 4; j++) acc[i][j] += a[i] * b[j];
        }
        __syncthreads();
    }

    #pragma unroll
    for (int i = 0; i < 8; i++) {
        int gm = bm + ty * 8 + i;
        if (gm >= M) continue;
        #pragma unroll
        for (int j = 0; j < 4; j++) {
            int gn = bn + tx * 4 + j;
            if (gn >= N) continue;
            float v = acc[i][j];
            if (bias) v += bias[gn];
            if (act == 1) v = tanhf(v);
            else if (act == 2) v = fmaxf(v, 0.f);
            C[(size_t)gm * N + gn] = v;
        }
    }
}

// ---------------- elementwise kernels ----------------
__global__ void k_zero(float* p, size_t n) {
    size_t i = (size_t)blockIdx.x * blockDim.x + threadIdx.x;
    if (i < n) p[i] = 0.f;
}
__global__ void k_copy(float* dst, const float* src, size_t n) {
    size_t i = (size_t)blockIdx.x * blockDim.x + threadIdx.x;
    if (i < n) dst[i] = src[i];
}
__global__ void k_add(float* dst, const float* src, size_t n) {
    size_t i = (size_t)blockIdx.x * blockDim.x + threadIdx.x;
    if (i < n) dst[i] += src[i];
}

// GRU gate update for timestep t (both directions use this)
__global__ void gru_pointwise(const float* __restrict__ xg, const float* __restrict__ hg,
                              float* __restrict__ h, const int* __restrict__ lens, int t)
{
    int idx = blockIdx.x * blockDim.x + threadIdx.x;
    if (idx >= BSEQ * DD) return;
    int b = idx / DD, d = idx - b * DD;
    const float* xr = xg + ((size_t)(b * LL + t)) * G3D;
    const float* hr = hg + (size_t)b * G3D;
    float r = sigm(xr[d] + hr[d]);
    float z = sigm(xr[DD + d] + hr[DD + d]);
    float n = tanhf(xr[2 * DD + d] + r * hr[2 * DD + d]);
    if (t < lens[b]) h[idx] = (1.f - z) * n + z * h[idx];
}

// x_rev[b,t] = x[b, clip(len-1-t, 0, L-1)]
__global__ void k_revgather(const float* __restrict__ x, const int* __restrict__ lens,
                            float* __restrict__ xrev)
{
    size_t idx = (size_t)blockIdx.x * blockDim.x + threadIdx.x;
    if (idx >= (size_t)BLTOT * DD) return;
    int d = idx % DD;
    int bt = idx / DD;
    int t = bt % LL;
    int b = bt / LL;
    int src = lens[b] - 1 - t;
    if (src < 0) src = 0;
    xrev[idx] = x[((size_t)b * LL + src) * DD + d];
}

__global__ void k_gather_feats(const float* __restrict__ pooled, const int* __restrict__ vidx,
                               float* __restrict__ feats)
{
    int idx = blockIdx.x * blockDim.x + threadIdx.x;
    if (idx >= NVOBJ * FF) return;
    int v = idx / FF, j = idx - v * FF;
    feats[idx] = pooled[(size_t)vidx[v] * FF + j];
}

// z = [facts*q, facts*m, |facts-q|, |facts-m|]  (row i = v*K+k)
__global__ void k_build_z(const float* __restrict__ facts, const float* __restrict__ q,
                          const float* __restrict__ m, float* __restrict__ z)
{
    size_t idx = (size_t)blockIdx.x * blockDim.x + threadIdx.x;
    if (idx >= (size_t)BSEQ * ZDIM) return;
    int c = idx % ZDIM;
    int i = idx / ZDIM;
    int v = i / KK;
    int d = c % DD;
    int sec = c / DD;
    float f = facts[(size_t)i * DD + d];
    float qv = q[(size_t)v * DD + d];
    float mv = m[(size_t)v * DD + d];
    float val;
    if (sec == 0)      val = f * qv;
    else if (sec == 1) val = f * mv;
    else if (sec == 2) val = fabsf(f - qv);
    else               val = fabsf(f - mv);
    z[idx] = val;
}

// per-v: s[k] = h1[v,k,:]·w2 + b; gate = softmax_k(s)
__global__ void k_score_softmax(const float* __restrict__ h1, const float* __restrict__ w2,
                                const float* __restrict__ w2b, float* __restrict__ gate)
{
    int v = blockIdx.x;
    int tid = threadIdx.x;
    int w = tid >> 5, lane = tid & 31;
    __shared__ float s[KK];
    const float* row = h1 + ((size_t)v * KK + w) * FF;
    float sum = 0.f;
    for (int j = lane; j < FF; j += 32) sum += row[j] * w2[j];
    #pragma unroll
    for (int o = 16; o > 0; o >>= 1) sum += __shfl_down_sync(0xffffffffu, sum, o);
    if (lane == 0) s[w] = sum + w2b[0];
    __syncthreads();
    if (tid == 0) {
        float mx = s[0];
        #pragma unroll
        for (int k = 1; k < KK; k++) mx = fmaxf(mx, s[k]);
        float tot = 0.f, e[KK];
        #pragma unroll
        for (int k = 0; k < KK; k++) { e[k] = expf(s[k] - mx); tot += e[k]; }
        #pragma unroll
        for (int k = 0; k < KK; k++) gate[v * KK + k] = e[k] / tot;
    }
}

__global__ void agru_pointwise(const float* __restrict__ fWr, const float* __restrict__ fWh,
                               const float* __restrict__ hUr, const float* __restrict__ hUh,
                               const float* __restrict__ gate, float* __restrict__ h, int t)
{
    int idx = blockIdx.x * blockDim.x + threadIdx.x;
    if (idx >= NVOBJ * DD) return;
    int v = idx / DD, d = idx - v * DD;
    int row = v * KK + t;
    float r = sigm(fWr[(size_t)row * DD + d] + hUr[idx]);
    float ht = tanhf(fWh[(size_t)row * DD + d] + r * hUh[idx]);
    float gt = gate[row];
    h[idx] = gt * ht + (1.f - gt) * h[idx];
}

__global__ void k_cat3(const float* __restrict__ m, const float* __restrict__ attn,
                       const float* __restrict__ q, float* __restrict__ cat)
{
    int idx = blockIdx.x * blockDim.x + threadIdx.x;
    if (idx >= NVOBJ * G3D) return;
    int v = idx / G3D, c = idx - v * G3D;
    float val;
    if (c < DD)           val = m[v * DD + c];
    else if (c < 2 * DD)  val = attn[v * DD + c - DD];
    else                  val = q[v * DD + c - 2 * DD];
    cat[idx] = val;
}

__global__ void k_cat2(const float* __restrict__ feats, const float* __restrict__ m,
                       float* __restrict__ cat)
{
    int idx = blockIdx.x * blockDim.x + threadIdx.x;
    if (idx >= NVOBJ * CAT2) return;
    int v = idx / CAT2, c = idx - v * CAT2;
    cat[idx] = (c < FF) ? feats[v * FF + c] : m[v * DD + (c - FF)];
}

__global__ void k_scatter(const float* __restrict__ upd, const int* __restrict__ vidx,
                          float* __restrict__ out)
{
    int idx = blockIdx.x * blockDim.x + threadIdx.x;
    if (idx >= NVOBJ * FF) return;
    int v = idx / FF, j = idx - v * FF;
    out[(size_t)vidx[v] * FF + j] = upd[idx];
}

// ---------------- host orchestration ----------------
static inline dim3 gemm_grid(int M, int N) {
    return dim3((N + 63) / 64, (M + 127) / 128);
}
#define EWG(n) ((int)(((n) + 255) / 256))

extern "C" void kernel_launch(void* const* d_in, const int* in_sizes, int n_in,
                              void* d_out, int out_size)
{
    const float* pooled  = (const float*)d_in[0];   // (4096, 512)
    const float* concept = (const float*)d_in[1];   // (2048, 8, 10, 300)
    const int*   seqlen  = (const int*)d_in[2];     // (2048, 8)
    const int*   vidx    = (const int*)d_in[3];     // (2048,)
    const float* Wih     = (const float*)d_in[4];   // (2, 900, 300)
    const float* Whh     = (const float*)d_in[5];   // (2, 900, 300)
    const float* bih     = (const float*)d_in[6];   // (2, 900)
    const float* bhh     = (const float*)d_in[7];   // (2, 900)
    const float* Wq_w    = (const float*)d_in[8];   // (300, 512)
    const float* Wq_b    = (const float*)d_in[9];
    const float* W1_w    = (const float*)d_in[10];  // (512, 1200)
    const float* W1_b    = (const float*)d_in[11];
    const float* W2_w    = (const float*)d_in[12];  // (1, 512)
    const float* W2_b    = (const float*)d_in[13];
    const float* aWr     = (const float*)d_in[14];  // (300, 300)
    const float* aUr     = (const float*)d_in[15];
    const float* abr     = (const float*)d_in[16];
    const float* aWh     = (const float*)d_in[17];
    const float* aUh     = (const float*)d_in[18];
    const float* abh     = (const float*)d_in[19];
    const float* nmt_w   = (const float*)d_in[20];  // (300, 900)
    const float* nmt_b   = (const float*)d_in[21];
    const float* upd_w   = (const float*)d_in[22];  // (512, 812)
    const float* upd_b   = (const float*)d_in[23];
    float* out = (float*)d_out;                     // (4096, 512)

    float *xg, *xrev, *hg, *h, *facts, *feats, *q, *m, *z, *h1, *gate;
    float *fWr, *fWh, *hUr, *hUh, *attn, *cat, *cat2, *upd;
    cudaGetSymbolAddress((void**)&xg, g_xg);
    cudaGetSymbolAddress((void**)&xrev, g_xrev);
    cudaGetSymbolAddress((void**)&hg, g_hg);
    cudaGetSymbolAddress((void**)&h, g_h);
    cudaGetSymbolAddress((void**)&facts, g_facts);
    cudaGetSymbolAddress((void**)&feats, g_feats);
    cudaGetSymbolAddress((void**)&q, g_q);
    cudaGetSymbolAddress((void**)&m, g_m);
    cudaGetSymbolAddress((void**)&z, g_z);
    cudaGetSymbolAddress((void**)&h1, g_h1);
    cudaGetSymbolAddress((void**)&gate, g_gate);
    cudaGetSymbolAddress((void**)&fWr, g_fWr);
    cudaGetSymbolAddress((void**)&fWh, g_fWh);
    cudaGetSymbolAddress((void**)&hUr, g_hUr);
    cudaGetSymbolAddress((void**)&hUh, g_hUh);
    cudaGetSymbolAddress((void**)&attn, g_attn);
    cudaGetSymbolAddress((void**)&cat, g_cat);
    cudaGetSymbolAddress((void**)&cat2, g_cat2);
    cudaGetSymbolAddress((void**)&upd, g_upd);

    // ===== bidirectional GRU fact embeddings =====
    for (int dir = 0; dir < 2; ++dir) {
        const float* Wih_d = Wih + (size_t)dir * G3D * DD;
        const float* Whh_d = Whh + (size_t)dir * G3D * DD;
        const float* bih_d = bih + dir * G3D;
        const float* bhh_d = bhh + dir * G3D;
        const float* X = concept;
        if (dir == 1) {
            k_revgather<<<EWG((size_t)BLTOT * DD), 256>>>(concept, seqlen, xrev);
            X = xrev;
        }
        // input-gate precompute for all timesteps: (163840,300)@(300,900)
        gemm_nt<<<gemm_grid(BLTOT, G3D), 256>>>(X, Wih_d, bih_d, xg, BLTOT, G3D, DD, 0);
        k_zero<<<EWG(BSEQ * DD), 256>>>(h, (size_t)BSEQ * DD);
        for (int t = 0; t < LL; ++t) {
            gemm_nt<<<gemm_grid(BSEQ, G3D), 256>>>(h, Whh_d, bhh_d, hg, BSEQ, G3D, DD, 0);
            gru_pointwise<<<EWG(BSEQ * DD), 256>>>(xg, hg, h, seqlen, t);
        }
        if (dir == 0) k_copy<<<EWG(BSEQ * DD), 256>>>(facts, h, (size_t)BSEQ * DD);
        else          k_add<<<EWG(BSEQ * DD), 256>>>(facts, h, (size_t)BSEQ * DD);
    }

    // ===== query =====
    k_gather_feats<<<EWG(NVOBJ * FF), 256>>>(pooled, vidx, feats);
    gemm_nt<<<gemm_grid(NVOBJ, DD), 256>>>(feats, Wq_w, Wq_b, q, NVOBJ, DD, FF, 1);
    k_copy<<<EWG(NVOBJ * DD), 256>>>(m, q, (size_t)NVOBJ * DD);

    // precompute facts@Wr^T+br, facts@Wh^T+bh (constant across T_M)
    gemm_nt<<<gemm_grid(BSEQ, DD), 256>>>(facts, aWr, abr, fWr, BSEQ, DD, DD, 0);
    gemm_nt<<<gemm_grid(BSEQ, DD), 256>>>(facts, aWh, abh, fWh, BSEQ, DD, DD, 0);

    // ===== episodic memory passes =====
    for (int it = 0; it < TM; ++it) {
        k_build_z<<<EWG((size_t)BSEQ * ZDIM), 256>>>(facts, q, m, z);
        gemm_nt<<<gemm_grid(BSEQ, FF), 256>>>(z, W1_w, W1_b, h1, BSEQ, FF, ZDIM, 1);
        k_score_softmax<<<NVOBJ, 256>>>(h1, W2_w, W2_b, gate);
        k_zero<<<EWG(NVOBJ * DD), 256>>>(attn, (size_t)NVOBJ * DD);
        for (int t = 0; t < KK; ++t) {
            gemm_nt<<<gemm_grid(NVOBJ, DD), 256>>>(attn, aUr, nullptr, hUr, NVOBJ, DD, DD, 0);
            gemm_nt<<<gemm_grid(NVOBJ, DD), 256>>>(attn, aUh, nullptr, hUh, NVOBJ, DD, DD, 0);
            agru_pointwise<<<EWG(NVOBJ * DD), 256>>>(fWr, fWh, hUr, hUh, gate, attn, t);
        }
        k_cat3<<<EWG(NVOBJ * G3D), 256>>>(m, attn, q, cat);
        gemm_nt<<<gemm_grid(NVOBJ, DD), 256>>>(cat, nmt_w, nmt_b, m, NVOBJ, DD, G3D, 2);
    }

    // ===== object update + scatter into output =====
    k_cat2<<<EWG(NVOBJ * CAT2), 256>>>(feats, m, cat2);
    gemm_nt<<<gemm_grid(NVOBJ, FF), 256>>>(cat2, upd_w, upd_b, upd, NVOBJ, FF, CAT2, 2);
    k_copy<<<EWG((size_t)NOBJ * FF), 256>>>(out, pooled, (size_t)NOBJ * FF);
    k_scatter<<<EWG(NVOBJ * FF), 256>>>(upd, vidx, out);
}

// round 3
// speedup vs baseline: 2.2862x; 2.2862x over previous
#include <cuda_runtime.h>
#include <cstdint>
#include <cstddef>

// Problem constants
#define NVOBJ 2048
#define KK    8
#define LL    10
#define DD    300
#define FF    512
#define NOBJ  4096
#define TM    3
#define BSEQ  (NVOBJ*KK)        // 16384
#define BLTOT (BSEQ*LL)         // 163840
#define G3D   (3*DD)            // 900
#define ZDIM  (4*DD)            // 1200
#define CAT2  (DD+FF)           // 812
#define D2    (2*DD)            // 600

// ---------------- scratch (device globals; no allocation) ----------------
__device__ float g_xg[(size_t)BLTOT*G3D];
__device__ float g_xrev[(size_t)BLTOT*DD];
__device__ float g_hg[(size_t)BSEQ*G3D];
__device__ float g_h[BSEQ*DD];
__device__ float g_facts[BSEQ*DD];
__device__ float g_feats[NVOBJ*FF];
__device__ float g_q[NVOBJ*DD];
__device__ float g_m[NVOBJ*DD];
__device__ float g_z[(size_t)BSEQ*ZDIM];
__device__ float g_h1[(size_t)BSEQ*FF];
__device__ float g_gate[BSEQ];
__device__ float g_U2[D2*DD];       // [Ur; Uh]
__device__ float g_W2cat[D2*DD];    // [Wr; Wh]
__device__ float g_b2cat[D2];
__device__ float g_fW2[(size_t)BSEQ*D2];
__device__ float g_hU2[NVOBJ*D2];
__device__ float g_attn[NVOBJ*DD];
__device__ float g_cat[NVOBJ*G3D];
__device__ float g_cat2[NVOBJ*CAT2];
__device__ float g_upd[NVOBJ*FF];

__device__ __forceinline__ float sigm(float x) { return 1.f / (1.f + expf(-x)); }

__device__ __forceinline__ uint32_t f2tf(float f) {
    uint32_t u;
    asm("cvt.rna.tf32.f32 %0, %1;" : "=r"(u) : "f"(f));
    return u;
}

__device__ __forceinline__ void mma_tf32(float c[4], uint32_t a0, uint32_t a1,
                                         uint32_t a2, uint32_t a3,
                                         uint32_t b0, uint32_t b1)
{
    asm volatile(
        "mma.sync.aligned.m16n8k8.row.col.f32.tf32.tf32.f32 "
        "{%0,%1,%2,%3}, {%4,%5,%6,%7}, {%8,%9}, {%0,%1,%2,%3};"
        : "+f"(c[0]), "+f"(c[1]), "+f"(c[2]), "+f"(c[3])
        : "r"(a0), "r"(a1), "r"(a2), "r"(a3), "r"(b0), "r"(b1));
}

// ---------------- tensor-core NT GEMM: C = act(A(M,K) @ B(N,K)^T + bias) --
// act: 0=none, 1=tanh, 2=relu. Requires K % 4 == 0, N even.
// BM=128, BN=64, BK=32. 256 threads = 8 warps (4 m x 2 n), warp tile 32x32.
#define SA 36   // padded k-stride (words) for As/Bs
__global__ __launch_bounds__(256) void gemm_nt_tc(
    const float* __restrict__ A, const float* __restrict__ B,
    const float* __restrict__ bias, float* __restrict__ C,
    int M, int N, int K, int act)
{
    __shared__ uint32_t As[128 * SA];
    __shared__ uint32_t Bs[64 * SA];

    const int bm = blockIdx.y * 128;
    const int bn = blockIdx.x * 64;
    const int tid = threadIdx.x;
    const int lane = tid & 31;
    const int warp = tid >> 5;
    const int wm = warp & 3;          // 0..3  -> 32-row strip
    const int wn = warp >> 2;         // 0..1  -> 32-col strip
    const int g = lane >> 2;          // 0..7
    const int c = lane & 3;           // 0..3
    const int row0 = wm * 32;
    const int col0 = wn * 32;

    float acc[2][4][4];
    #pragma unroll
    for (int i = 0; i < 2; i++)
        #pragma unroll
        for (int j = 0; j < 4; j++)
            #pragma unroll
            for (int l = 0; l < 4; l++) acc[i][j][l] = 0.f;

    // staging indices
    const int ar = tid >> 1;              // A row 0..127
    const int akq = (tid & 1) * 16;       // A k offset 0/16
    const int brow = tid >> 2;            // B row 0..63
    const int bkq = (tid & 3) * 8;        // B k offset

    for (int k0 = 0; k0 < K; k0 += 32) {
        // ---- stage A: 128x32, 4 float4/thread ----
        {
            int gm = bm + ar;
            const float* Arow = A + (size_t)gm * K;
            #pragma unroll
            for (int i = 0; i < 4; ++i) {
                int gk = k0 + akq + i * 4;
                uint4 o = make_uint4(0u, 0u, 0u, 0u);
                if (gm < M && gk < K) {
                    float4 v = *reinterpret_cast<const float4*>(Arow + gk);
                    o.x = f2tf(v.x); o.y = f2tf(v.y);
                    o.z = f2tf(v.z); o.w = f2tf(v.w);
                }
                *reinterpret_cast<uint4*>(&As[ar * SA + akq + i * 4]) = o;
            }
        }
        // ---- stage B: 64x32, 2 float4/thread ----
        {
            int gn = bn + brow;
            const float* Brow = B + (size_t)gn * K;
            #pragma unroll
            for (int i = 0; i < 2; ++i) {
                int gk = k0 + bkq + i * 4;
                uint4 o = make_uint4(0u, 0u, 0u, 0u);
                if (gn < N && gk < K) {
                    float4 v = *reinterpret_cast<const float4*>(Brow + gk);
                    o.x = f2tf(v.x); o.y = f2tf(v.y);
                    o.z = f2tf(v.z); o.w = f2tf(v.w);
                }
                *reinterpret_cast<uint4*>(&Bs[brow * SA + bkq + i * 4]) = o;
            }
        }
        __syncthreads();

        #pragma unroll
        for (int ks = 0; ks < 4; ++ks) {
            const int kbase = ks * 8;
            // A fragments: a0=(g,c) a1=(g+8,c) a2=(g,c+4) a3=(g+8,c+4)
            uint32_t a[2][4];
            #pragma unroll
            for (int mm = 0; mm < 2; ++mm) {
                int base = (row0 + mm * 16 + g) * SA + kbase;
                a[mm][0] = As[base + c];
                a[mm][1] = As[base + 8 * SA + c];
                a[mm][2] = As[base + c + 4];
                a[mm][3] = As[base + 8 * SA + c + 4];
            }
            #pragma unroll
            for (int nn = 0; nn < 4; ++nn) {
                // B fragments: b0=(n=g,k=c) b1=(n=g,k=c+4)
                int rb = (col0 + nn * 8 + g) * SA + kbase;
                uint32_t b0 = Bs[rb + c];
                uint32_t b1 = Bs[rb + c + 4];
                #pragma unroll
                for (int mm = 0; mm < 2; ++mm) {
                    mma_tf32(acc[mm][nn], a[mm][0], a[mm][1], a[mm][2], a[mm][3],
                             b0, b1);
                }
            }
        }
        __syncthreads();
    }

    // ---- epilogue ----
    #pragma unroll
    for (int mm = 0; mm < 2; ++mm) {
        int gm0 = bm + row0 + mm * 16 + g;
        #pragma unroll
        for (int nn = 0; nn < 4; ++nn) {
            int gn = bn + col0 + nn * 8 + 2 * c;
            if (gn >= N) continue;
            float b0 = 0.f, b1 = 0.f;
            if (bias) { b0 = bias[gn]; b1 = bias[gn + 1]; }
            #pragma unroll
            for (int half = 0; half < 2; ++half) {
                int gm = gm0 + half * 8;
                if (gm >= M) continue;
                float v0 = acc[mm][nn][half * 2 + 0] + b0;
                float v1 = acc[mm][nn][half * 2 + 1] + b1;
                if (act == 1) { v0 = tanhf(v0); v1 = tanhf(v1); }
                else if (act == 2) { v0 = fmaxf(v0, 0.f); v1 = fmaxf(v1, 0.f); }
                *reinterpret_cast<float2*>(C + (size_t)gm * N + gn) =
                    make_float2(v0, v1);
            }
        }
    }
}

// ---------------- elementwise kernels ----------------
__global__ void k_zero(float* p, size_t n) {
    size_t i = (size_t)blockIdx.x * blockDim.x + threadIdx.x;
    if (i < n) p[i] = 0.f;
}
__global__ void k_copy(float* dst, const float* src, size_t n) {
    size_t i = (size_t)blockIdx.x * blockDim.x + threadIdx.x;
    if (i < n) dst[i] = src[i];
}
__global__ void k_add(float* dst, const float* src, size_t n) {
    size_t i = (size_t)blockIdx.x * blockDim.x + threadIdx.x;
    if (i < n) dst[i] += src[i];
}

// GRU gate update for timestep t (float4 vectorized; DD%4==0)
__global__ void gru_pointwise4(const float* __restrict__ xg, const float* __restrict__ hg,
                               float* __restrict__ h, const int* __restrict__ lens, int t)
{
    int idx = blockIdx.x * blockDim.x + threadIdx.x;
    if (idx >= BSEQ * (DD / 4)) return;
    int b = idx / (DD / 4);
    int d = (idx - b * (DD / 4)) * 4;
    if (t >= lens[b]) return;
    const float* xr = xg + ((size_t)(b * LL + t)) * G3D;
    const float* hr = hg + (size_t)b * G3D;
    float4 xrv = *reinterpret_cast<const float4*>(xr + d);
    float4 xzv = *reinterpret_cast<const float4*>(xr + DD + d);
    float4 xnv = *reinterpret_cast<const float4*>(xr + 2 * DD + d);
    float4 hrv = *reinterpret_cast<const float4*>(hr + d);
    float4 hzv = *reinterpret_cast<const float4*>(hr + DD + d);
    float4 hnv = *reinterpret_cast<const float4*>(hr + 2 * DD + d);
    float4 hv  = *reinterpret_cast<float4*>(h + (size_t)b * DD + d);
    float4 o;
    {
        float r = sigm(xrv.x + hrv.x), z = sigm(xzv.x + hzv.x);
        float n = tanhf(xnv.x + r * hnv.x); o.x = (1.f - z) * n + z * hv.x;
    }
    {
        float r = sigm(xrv.y + hrv.y), z = sigm(xzv.y + hzv.y);
        float n = tanhf(xnv.y + r * hnv.y); o.y = (1.f - z) * n + z * hv.y;
    }
    {
        float r = sigm(xrv.z + hrv.z), z = sigm(xzv.z + hzv.z);
        float n = tanhf(xnv.z + r * hnv.z); o.z = (1.f - z) * n + z * hv.z;
    }
    {
        float r = sigm(xrv.w + hrv.w), z = sigm(xzv.w + hzv.w);
        float n = tanhf(xnv.w + r * hnv.w); o.w = (1.f - z) * n + z * hv.w;
    }
    *reinterpret_cast<float4*>(h + (size_t)b * DD + d) = o;
}

// x_rev[b,t] = x[b, clip(len-1-t, 0, L-1)]
__global__ void k_revgather(const float* __restrict__ x, const int* __restrict__ lens,
                            float* __restrict__ xrev)
{
    size_t idx = (size_t)blockIdx.x * blockDim.x + threadIdx.x;
    if (idx >= (size_t)BLTOT * (DD / 4)) return;
    int d = (idx % (DD / 4)) * 4;
    size_t bt = idx / (DD / 4);
    int t = bt % LL;
    int b = bt / LL;
    int src = lens[b] - 1 - t;
    if (src < 0) src = 0;
    *reinterpret_cast<float4*>(xrev + bt * DD + d) =
        *reinterpret_cast<const float4*>(x + ((size_t)b * LL + src) * DD + d);
}

__global__ void k_gather_feats(const float* __restrict__ pooled, const int* __restrict__ vidx,
                               float* __restrict__ feats)
{
    int idx = blockIdx.x * blockDim.x + threadIdx.x;
    if (idx >= NVOBJ * (FF / 4)) return;
    int v = idx / (FF / 4), j = (idx - v * (FF / 4)) * 4;
    *reinterpret_cast<float4*>(feats + (size_t)v * FF + j) =
        *reinterpret_cast<const float4*>(pooled + (size_t)vidx[v] * FF + j);
}

// z = [facts*q, facts*m, |facts-q|, |facts-m|]
__global__ void k_build_z(const float* __restrict__ facts, const float* __restrict__ q,
                          const float* __restrict__ m, float* __restrict__ z)
{
    size_t idx = (size_t)blockIdx.x * blockDim.x + threadIdx.x;
    if (idx >= (size_t)BSEQ * DD) return;
    int d = idx % DD;
    int i = idx / DD;
    int v = i / KK;
    float f = facts[idx];
    float qv = q[(size_t)v * DD + d];
    float mv = m[(size_t)v * DD + d];
    float* zr = z + (size_t)i * ZDIM;
    zr[d] = f * qv;
    zr[DD + d] = f * mv;
    zr[2 * DD + d] = fabsf(f - qv);
    zr[3 * DD + d] = fabsf(f - mv);
}

// per-v: s[k] = h1[v,k,:]·w2 + b; gate = softmax_k(s)
__global__ void k_score_softmax(const float* __restrict__ h1, const float* __restrict__ w2,
                                const float* __restrict__ w2b, float* __restrict__ gate)
{
    int v = blockIdx.x;
    int tid = threadIdx.x;
    int w = tid >> 5, lane = tid & 31;
    __shared__ float s[KK];
    const float* row = h1 + ((size_t)v * KK + w) * FF;
    float sum = 0.f;
    for (int j = lane; j < FF; j += 32) sum += row[j] * w2[j];
    #pragma unroll
    for (int o = 16; o > 0; o >>= 1) sum += __shfl_down_sync(0xffffffffu, sum, o);
    if (lane == 0) s[w] = sum + w2b[0];
    __syncthreads();
    if (tid == 0) {
        float mx = s[0];
        #pragma unroll
        for (int k = 1; k < KK; k++) mx = fmaxf(mx, s[k]);
        float tot = 0.f, e[KK];
        #pragma unroll
        for (int k = 0; k < KK; k++) { e[k] = expf(s[k] - mx); tot += e[k]; }
        #pragma unroll
        for (int k = 0; k < KK; k++) gate[v * KK + k] = e[k] / tot;
    }
}

// AGRU pointwise with fused [Wr;Wh] and [Ur;Uh] precomputes
__global__ void agru_pointwise4(const float* __restrict__ fW2, const float* __restrict__ hU2,
                                const float* __restrict__ gate, float* __restrict__ h, int t)
{
    int idx = blockIdx.x * blockDim.x + threadIdx.x;
    if (idx >= NVOBJ * (DD / 4)) return;
    int v = idx / (DD / 4);
    int d = (idx - v * (DD / 4)) * 4;
    int row = v * KK + t;
    float4 fr = *reinterpret_cast<const float4*>(fW2 + (size_t)row * D2 + d);
    float4 fh = *reinterpret_cast<const float4*>(fW2 + (size_t)row * D2 + DD + d);
    float4 ur = *reinterpret_cast<const float4*>(hU2 + (size_t)v * D2 + d);
    float4 uh = *reinterpret_cast<const float4*>(hU2 + (size_t)v * D2 + DD + d);
    float4 hv = *reinterpret_cast<float4*>(h + (size_t)v * DD + d);
    float gt = gate[row];
    float4 o;
    { float r = sigm(fr.x + ur.x); float ht = tanhf(fh.x + r * uh.x); o.x = gt * ht + (1.f - gt) * hv.x; }
    { float r = sigm(fr.y + ur.y); float ht = tanhf(fh.y + r * uh.y); o.y = gt * ht + (1.f - gt) * hv.y; }
    { float r = sigm(fr.z + ur.z); float ht = tanhf(fh.z + r * uh.z); o.z = gt * ht + (1.f - gt) * hv.z; }
    { float r = sigm(fr.w + ur.w); float ht = tanhf(fh.w + r * uh.w); o.w = gt * ht + (1.f - gt) * hv.w; }
    *reinterpret_cast<float4*>(h + (size_t)v * DD + d) = o;
}

__global__ void k_cat3(const float* __restrict__ m, const float* __restrict__ attn,
                       const float* __restrict__ q, float* __restrict__ cat)
{
    int idx = blockIdx.x * blockDim.x + threadIdx.x;
    if (idx >= NVOBJ * G3D) return;
    int v = idx / G3D, c = idx - v * G3D;
    float val;
    if (c < DD)           val = m[v * DD + c];
    else if (c < 2 * DD)  val = attn[v * DD + c - DD];
    else                  val = q[v * DD + c - 2 * DD];
    cat[idx] = val;
}

__global__ void k_cat2(const float* __restrict__ feats, const float* __restrict__ m,
                       float* __restrict__ cat)
{
    int idx = blockIdx.x * blockDim.x + threadIdx.x;
    if (idx >= NVOBJ * CAT2) return;
    int v = idx / CAT2, c = idx - v * CAT2;
    cat[idx] = (c < FF) ? feats[v * FF + c] : m[v * DD + (c - FF)];
}

__global__ void k_scatter(const float* __restrict__ upd, const int* __restrict__ vidx,
                          float* __restrict__ out)
{
    int idx = blockIdx.x * blockDim.x + threadIdx.x;
    if (idx >= NVOBJ * FF) return;
    int v = idx / FF, j = idx - v * FF;
    out[(size_t)vidx[v] * FF + j] = upd[idx];
}

// ---------------- host orchestration ----------------
static inline dim3 gemm_grid(int M, int N) {
    return dim3((N + 63) / 64, (M + 127) / 128);
}
#define EWG(n) ((int)(((n) + 255) / 256))

extern "C" void kernel_launch(void* const* d_in, const int* in_sizes, int n_in,
                              void* d_out, int out_size)
{
    const float* pooled  = (const float*)d_in[0];
    const float* concept = (const float*)d_in[1];
    const int*   seqlen  = (const int*)d_in[2];
    const int*   vidx    = (const int*)d_in[3];
    const float* Wih     = (const float*)d_in[4];
    const float* Whh     = (const float*)d_in[5];
    const float* bih     = (const float*)d_in[6];
    const float* bhh     = (const float*)d_in[7];
    const float* Wq_w    = (const float*)d_in[8];
    const float* Wq_b    = (const float*)d_in[9];
    const float* W1_w    = (const float*)d_in[10];
    const float* W1_b    = (const float*)d_in[11];
    const float* W2_w    = (const float*)d_in[12];
    const float* W2_b    = (const float*)d_in[13];
    const float* aWr     = (const float*)d_in[14];
    const float* aUr     = (const float*)d_in[15];
    const float* abr     = (const float*)d_in[16];
    const float* aWh     = (const float*)d_in[17];
    const float* aUh     = (const float*)d_in[18];
    const float* abh     = (const float*)d_in[19];
    const float* nmt_w   = (const float*)d_in[20];
    const float* nmt_b   = (const float*)d_in[21];
    const float* upd_w   = (const float*)d_in[22];
    const float* upd_b   = (const float*)d_in[23];
    float* out = (float*)d_out;

    float *xg, *xrev, *hg, *h, *facts, *feats, *q, *m, *z, *h1, *gate;
    float *U2, *W2cat, *b2cat, *fW2, *hU2, *attn, *cat, *cat2, *upd;
    cudaGetSymbolAddress((void**)&xg, g_xg);
    cudaGetSymbolAddress((void**)&xrev, g_xrev);
    cudaGetSymbolAddress((void**)&hg, g_hg);
    cudaGetSymbolAddress((void**)&h, g_h);
    cudaGetSymbolAddress((void**)&facts, g_facts);
    cudaGetSymbolAddress((void**)&feats, g_feats);
    cudaGetSymbolAddress((void**)&q, g_q);
    cudaGetSymbolAddress((void**)&m, g_m);
    cudaGetSymbolAddress((void**)&z, g_z);
    cudaGetSymbolAddress((void**)&h1, g_h1);
    cudaGetSymbolAddress((void**)&gate, g_gate);
    cudaGetSymbolAddress((void**)&U2, g_U2);
    cudaGetSymbolAddress((void**)&W2cat, g_W2cat);
    cudaGetSymbolAddress((void**)&b2cat, g_b2cat);
    cudaGetSymbolAddress((void**)&fW2, g_fW2);
    cudaGetSymbolAddress((void**)&hU2, g_hU2);
    cudaGetSymbolAddress((void**)&attn, g_attn);
    cudaGetSymbolAddress((void**)&cat, g_cat);
    cudaGetSymbolAddress((void**)&cat2, g_cat2);
    cudaGetSymbolAddress((void**)&upd, g_upd);

    // ===== bidirectional GRU fact embeddings =====
    for (int dir = 0; dir < 2; ++dir) {
        const float* Wih_d = Wih + (size_t)dir * G3D * DD;
        const float* Whh_d = Whh + (size_t)dir * G3D * DD;
        const float* bih_d = bih + dir * G3D;
        const float* bhh_d = bhh + dir * G3D;
        const float* X = concept;
        if (dir == 1) {
            k_revgather<<<EWG((size_t)BLTOT * (DD / 4)), 256>>>(concept, seqlen, xrev);
            X = xrev;
        }
        gemm_nt_tc<<<gemm_grid(BLTOT, G3D), 256>>>(X, Wih_d, bih_d, xg, BLTOT, G3D, DD, 0);
        k_zero<<<EWG(BSEQ * DD), 256>>>(h, (size_t)BSEQ * DD);
        for (int t = 0; t < LL; ++t) {
            gemm_nt_tc<<<gemm_grid(BSEQ, G3D), 256>>>(h, Whh_d, bhh_d, hg, BSEQ, G3D, DD, 0);
            gru_pointwise4<<<EWG(BSEQ * (DD / 4)), 256>>>(xg, hg, h, seqlen, t);
        }
        if (dir == 0) k_copy<<<EWG(BSEQ * DD), 256>>>(facts, h, (size_t)BSEQ * DD);
        else          k_add<<<EWG(BSEQ * DD), 256>>>(facts, h, (size_t)BSEQ * DD);
    }

    // ===== query =====
    k_gather_feats<<<EWG(NVOBJ * (FF / 4)), 256>>>(pooled, vidx, feats);
    gemm_nt_tc<<<gemm_grid(NVOBJ, DD), 256>>>(feats, Wq_w, Wq_b, q, NVOBJ, DD, FF, 1);
    k_copy<<<EWG(NVOBJ * DD), 256>>>(m, q, (size_t)NVOBJ * DD);

    // ===== build fused AGRU weights [Wr;Wh], [Ur;Uh], [br;bh] =====
    k_copy<<<EWG(DD * DD), 256>>>(W2cat, aWr, (size_t)DD * DD);
    k_copy<<<EWG(DD * DD), 256>>>(W2cat + DD * DD, aWh, (size_t)DD * DD);
    k_copy<<<EWG(DD * DD), 256>>>(U2, aUr, (size_t)DD * DD);
    k_copy<<<EWG(DD * DD), 256>>>(U2 + DD * DD, aUh, (size_t)DD * DD);
    k_copy<<<EWG(DD), 256>>>(b2cat, abr, (size_t)DD);
    k_copy<<<EWG(DD), 256>>>(b2cat + DD, abh, (size_t)DD);

    // precompute facts@[Wr;Wh]^T + [br;bh]  (constant across T_M)
    gemm_nt_tc<<<gemm_grid(BSEQ, D2), 256>>>(facts, W2cat, b2cat, fW2, BSEQ, D2, DD, 0);

    // ===== episodic memory passes =====
    for (int it = 0; it < TM; ++it) {
        k_build_z<<<EWG((size_t)BSEQ * DD), 256>>>(facts, q, m, z);
        gemm_nt_tc<<<gemm_grid(BSEQ, FF), 256>>>(z, W1_w, W1_b, h1, BSEQ, FF, ZDIM, 1);
        k_score_softmax<<<NVOBJ, 256>>>(h1, W2_w, W2_b, gate);
        k_zero<<<EWG(NVOBJ * DD), 256>>>(attn, (size_t)NVOBJ * DD);
        for (int t = 0; t < KK; ++t) {
            gemm_nt_tc<<<gemm_grid(NVOBJ, D2), 256>>>(attn, U2, nullptr, hU2, NVOBJ, D2, DD, 0);
            agru_pointwise4<<<EWG(NVOBJ * (DD / 4)), 256>>>(fW2, hU2, gate, attn, t);
        }
        k_cat3<<<EWG(NVOBJ * G3D), 256>>>(m, attn, q, cat);
        gemm_nt_tc<<<gemm_grid(NVOBJ, DD), 256>>>(cat, nmt_w, nmt_b, m, NVOBJ, DD, G3D, 2);
    }

    // ===== object update + scatter into output =====
    k_cat2<<<EWG(NVOBJ * CAT2), 256>>>(feats, m, cat2);
    gemm_nt_tc<<<gemm_grid(NVOBJ, FF), 256>>>(cat2, upd_w, upd_b, upd, NVOBJ, FF, CAT2, 2);
    k_copy<<<EWG((size_t)NOBJ * FF), 256>>>(out, pooled, (size_t)NOBJ * FF);
    k_scatter<<<EWG(NVOBJ * FF), 256>>>(upd, vidx, out);
}

// round 4
// speedup vs baseline: 3.2309x; 1.4132x over previous
#include <cuda_runtime.h>
#include <cstdint>
#include <cstddef>

// Problem constants
#define NVOBJ 2048
#define KK    8
#define LL    10
#define DD    300
#define FF    512
#define NOBJ  4096
#define TM    3
#define BSEQ  (NVOBJ*KK)        // 16384
#define BLTOT (BSEQ*LL)         // 163840
#define G3D   (3*DD)            // 900
#define ZDIM  (4*DD)            // 1200
#define CAT2  (DD+FF)           // 812
#define D2    (2*DD)            // 600
#define D4    (DD/4)            // 75

// ---------------- scratch (device globals; no allocation) ----------------
__device__ float g_xg[(size_t)BLTOT*G3D];   // packed time-major input gates
__device__ float g_xp[(size_t)BLTOT*DD];    // packed time-major inputs
__device__ float g_hg[(size_t)BSEQ*G3D];
__device__ float g_h[BSEQ*DD];              // forward hidden (packed)
__device__ float g_hb[BSEQ*DD];             // backward hidden (packed)
__device__ float g_facts[BSEQ*DD];
__device__ float g_feats[NVOBJ*FF];
__device__ float g_q[NVOBJ*DD];
__device__ float g_m[NVOBJ*DD];
__device__ float g_z[(size_t)BSEQ*ZDIM];
__device__ float g_h1[(size_t)BSEQ*FF];
__device__ float g_gate[BSEQ];
__device__ float g_U2[D2*DD];       // [Ur; Uh]
__device__ float g_W2cat[D2*DD];    // [Wr; Wh]
__device__ float g_b2cat[D2];
__device__ float g_fW2[(size_t)BSEQ*D2];
__device__ float g_hU2[NVOBJ*D2];
__device__ float g_attn[NVOBJ*DD];
__device__ float g_cat[NVOBJ*G3D];
__device__ float g_cat2[NVOBJ*CAT2];
__device__ float g_upd[NVOBJ*FF];
// packing metadata
__device__ int g_cnt[16];
__device__ int g_basec[16];
__device__ int g_cursor[16];
__device__ int g_nact[LL + 2];   // n_active[t] = #seqs with len > t
__device__ int g_perm[BSEQ];

__device__ __forceinline__ float sigm(float x) { return 1.f / (1.f + expf(-x)); }

__device__ __forceinline__ void mma_tf32(float c[4], uint32_t a0, uint32_t a1,
                                         uint32_t a2, uint32_t a3,
                                         uint32_t b0, uint32_t b1)
{
    asm volatile(
        "mma.sync.aligned.m16n8k8.row.col.f32.tf32.tf32.f32 "
        "{%0,%1,%2,%3}, {%4,%5,%6,%7}, {%8,%9}, {%0,%1,%2,%3};"
        : "+f"(c[0]), "+f"(c[1]), "+f"(c[2]), "+f"(c[3])
        : "r"(a0), "r"(a1), "r"(a2), "r"(a3), "r"(b0), "r"(b1));
}

__device__ __forceinline__ void cp_async16(uint32_t saddr, const void* g, bool valid)
{
    int sz = valid ? 16 : 0;
    asm volatile("cp.async.cg.shared.global [%0], [%1], 16, %2;\n"
                 :: "r"(saddr), "l"(g), "r"(sz));
}
__device__ __forceinline__ void cp_commit() {
    asm volatile("cp.async.commit_group;\n" ::: "memory");
}

// ---------------- tensor-core NT GEMM: C = act(A(M,K) @ B(N,K)^T + bias) --
// act: 0=none, 1=tanh, 2=relu. Requires K % 4 == 0.
// BM=128, BN=64, BK=32, double-buffered cp.async. 256 thr = 8 warps (4m x 2n).
// If limits != nullptr: block exits when (bm & ((1<<limshift)-1)) >= limits[bm>>limshift].
#define SA 36   // padded k-stride (words)
__global__ __launch_bounds__(256) void gemm_nt_tc(
    const float* __restrict__ A, const float* __restrict__ B,
    const float* __restrict__ bias, float* __restrict__ C,
    int M, int N, int K, int act,
    const int* __restrict__ limits, int limshift)
{
    __shared__ uint32_t As[2][128 * SA];
    __shared__ uint32_t Bs[2][64 * SA];

    const int bm = blockIdx.y * 128;
    const int bn = blockIdx.x * 64;
    if (limits) {
        int lim = __ldg(limits + (bm >> limshift));
        if ((bm & ((1 << limshift) - 1)) >= lim) return;
    }
    const int tid = threadIdx.x;
    const int lane = tid & 31;
    const int warp = tid >> 5;
    const int wm = warp & 3;
    const int wn = warp >> 2;
    const int g = lane >> 2;
    const int c = lane & 3;
    const int row0 = wm * 32;
    const int col0 = wn * 32;

    float acc[2][4][4];
    #pragma unroll
    for (int i = 0; i < 2; i++)
        #pragma unroll
        for (int j = 0; j < 4; j++)
            #pragma unroll
            for (int l = 0; l < 4; l++) acc[i][j][l] = 0.f;

    const int ar = tid >> 1;
    const int akq = (tid & 1) * 16;
    const int brow = tid >> 2;
    const int bkq = (tid & 3) * 8;

    const int gmA = bm + ar;
    const float* Arow = A + (size_t)(gmA < M ? gmA : M - 1) * K;
    const int gnB = bn + brow;
    const float* Brow = B + (size_t)(gnB < N ? gnB : N - 1) * K;

    const int ntiles = (K + 31) / 32;

    auto stage = [&](int s, int k0) {
        #pragma unroll
        for (int i = 0; i < 4; ++i) {
            int gk = k0 + akq + i * 4;
            bool v = (gmA < M) && (gk < K);
            int gkc = gk < K - 4 ? gk : K - 4;
            cp_async16((uint32_t)__cvta_generic_to_shared(&As[s][ar * SA + akq + i * 4]),
                       Arow + gkc, v);
        }
        #pragma unroll
        for (int i = 0; i < 2; ++i) {
            int gk = k0 + bkq + i * 4;
            bool v = (gnB < N) && (gk < K);
            int gkc = gk < K - 4 ? gk : K - 4;
            cp_async16((uint32_t)__cvta_generic_to_shared(&Bs[s][brow * SA + bkq + i * 4]),
                       Brow + gkc, v);
        }
    };

    stage(0, 0);
    cp_commit();
    int buf = 0;

    for (int it = 0; it < ntiles; ++it) {
        if (it + 1 < ntiles) {
            stage(buf ^ 1, (it + 1) * 32);
            cp_commit();
            asm volatile("cp.async.wait_group 1;\n" ::: "memory");
        } else {
            asm volatile("cp.async.wait_group 0;\n" ::: "memory");
        }
        __syncthreads();

        #pragma unroll
        for (int ks = 0; ks < 4; ++ks) {
            const int kbase = ks * 8;
            uint32_t a[2][4];
            #pragma unroll
            for (int mm = 0; mm < 2; ++mm) {
                int base = (row0 + mm * 16 + g) * SA + kbase;
                a[mm][0] = As[buf][base + c];
                a[mm][1] = As[buf][base + 8 * SA + c];
                a[mm][2] = As[buf][base + c + 4];
                a[mm][3] = As[buf][base + 8 * SA + c + 4];
            }
            #pragma unroll
            for (int nn = 0; nn < 4; ++nn) {
                int rb = (col0 + nn * 8 + g) * SA + kbase;
                uint32_t b0 = Bs[buf][rb + c];
                uint32_t b1 = Bs[buf][rb + c + 4];
                #pragma unroll
                for (int mm = 0; mm < 2; ++mm) {
                    mma_tf32(acc[mm][nn], a[mm][0], a[mm][1], a[mm][2], a[mm][3],
                             b0, b1);
                }
            }
        }
        __syncthreads();
        buf ^= 1;
    }

    // ---- epilogue ----
    #pragma unroll
    for (int mm = 0; mm < 2; ++mm) {
        int gm0 = bm + row0 + mm * 16 + g;
        #pragma unroll
        for (int nn = 0; nn < 4; ++nn) {
            int gn = bn + col0 + nn * 8 + 2 * c;
            if (gn >= N) continue;
            float b0 = 0.f, b1 = 0.f;
            if (bias) { b0 = bias[gn]; b1 = bias[gn + 1]; }
            #pragma unroll
            for (int half = 0; half < 2; ++half) {
                int gm = gm0 + half * 8;
                if (gm >= M) continue;
                float v0 = acc[mm][nn][half * 2 + 0] + b0;
                float v1 = acc[mm][nn][half * 2 + 1] + b1;
                if (act == 1) { v0 = tanhf(v0); v1 = tanhf(v1); }
                else if (act == 2) { v0 = fmaxf(v0, 0.f); v1 = fmaxf(v1, 0.f); }
                *reinterpret_cast<float2*>(C + (size_t)gm * N + gn) =
                    make_float2(v0, v1);
            }
        }
    }
}

// ---------------- packing (length sort) ----------------
__global__ void k_sort_init() {
    int i = threadIdx.x;
    if (i < 16) { g_cnt[i] = 0; }
}
__global__ void k_hist(const int* __restrict__ lens) {
    int b = blockIdx.x * blockDim.x + threadIdx.x;
    if (b < BSEQ) atomicAdd(&g_cnt[lens[b]], 1);
}
__global__ void k_base() {
    if (threadIdx.x == 0) {
        int off = 0;
        for (int l = LL; l >= 1; --l) {
            g_basec[l] = off;
            g_cursor[l] = off;
            off += g_cnt[l];
        }
        for (int t = 0; t < LL; ++t)
            g_nact[t] = g_basec[t + 1] + g_cnt[t + 1];   // #len > t
    }
}
__global__ void k_perm(const int* __restrict__ lens) {
    int b = blockIdx.x * blockDim.x + threadIdx.x;
    if (b < BSEQ) {
        int pos = atomicAdd(&g_cursor[lens[b]], 1);
        g_perm[pos] = b;
    }
}

// pack x into time-major layout: xp[t*BSEQ+pos] = x[perm[pos], srct]
// dir=0: srct = t ; dir=1: srct = len-1-t (active rows only)
__global__ void k_pack_x(const float* __restrict__ x, const int* __restrict__ lens,
                         float* __restrict__ xp, int dir)
{
    size_t idx = (size_t)blockIdx.x * blockDim.x + threadIdx.x;
    if (idx >= (size_t)BLTOT * D4) return;
    int d = (int)(idx % D4) * 4;
    size_t row = idx / D4;
    int t = (int)(row >> 14);
    int pos = (int)(row & 16383);
    if (pos >= g_nact[t]) return;
    int b = g_perm[pos];
    int srct = dir ? (lens[b] - 1 - t) : t;
    *reinterpret_cast<float4*>(xp + row * DD + d) =
        *reinterpret_cast<const float4*>(x + ((size_t)b * LL + srct) * DD + d);
}

// GRU gate update, packed rows [0, nact[t])
__global__ void gru_pointwise4(const float* __restrict__ xg, const float* __restrict__ hg,
                               float* __restrict__ h, int t)
{
    int idx = blockIdx.x * blockDim.x + threadIdx.x;
    if (idx >= BSEQ * D4) return;
    int pos = idx / D4;
    if (pos >= g_nact[t]) return;
    int d = (idx - pos * D4) * 4;
    const float* xr = xg + ((size_t)t * BSEQ + pos) * G3D;
    const float* hr = hg + (size_t)pos * G3D;
    float4 xrv = *reinterpret_cast<const float4*>(xr + d);
    float4 xzv = *reinterpret_cast<const float4*>(xr + DD + d);
    float4 xnv = *reinterpret_cast<const float4*>(xr + 2 * DD + d);
    float4 hrv = *reinterpret_cast<const float4*>(hr + d);
    float4 hzv = *reinterpret_cast<const float4*>(hr + DD + d);
    float4 hnv = *reinterpret_cast<const float4*>(hr + 2 * DD + d);
    float4 hv  = *reinterpret_cast<float4*>(h + (size_t)pos * DD + d);
    float4 o;
    { float r = sigm(xrv.x + hrv.x), z = sigm(xzv.x + hzv.x);
      float n = tanhf(xnv.x + r * hnv.x); o.x = (1.f - z) * n + z * hv.x; }
    { float r = sigm(xrv.y + hrv.y), z = sigm(xzv.y + hzv.y);
      float n = tanhf(xnv.y + r * hnv.y); o.y = (1.f - z) * n + z * hv.y; }
    { float r = sigm(xrv.z + hrv.z), z = sigm(xzv.z + hzv.z);
      float n = tanhf(xnv.z + r * hnv.z); o.z = (1.f - z) * n + z * hv.z; }
    { float r = sigm(xrv.w + hrv.w), z = sigm(xzv.w + hzv.w);
      float n = tanhf(xnv.w + r * hnv.w); o.w = (1.f - z) * n + z * hv.w; }
    *reinterpret_cast<float4*>(h + (size_t)pos * DD + d) = o;
}

// facts[perm[pos]] = hf[pos] + hb[pos]
__global__ void k_unpack_facts(const float* __restrict__ hf, const float* __restrict__ hb,
                               float* __restrict__ facts)
{
    int idx = blockIdx.x * blockDim.x + threadIdx.x;
    if (idx >= BSEQ * D4) return;
    int pos = idx / D4;
    int d = (idx - pos * D4) * 4;
    int b = g_perm[pos];
    float4 a = *reinterpret_cast<const float4*>(hf + (size_t)pos * DD + d);
    float4 bb = *reinterpret_cast<const float4*>(hb + (size_t)pos * DD + d);
    *reinterpret_cast<float4*>(facts + (size_t)b * DD + d) =
        make_float4(a.x + bb.x, a.y + bb.y, a.z + bb.z, a.w + bb.w);
}

// ---------------- misc elementwise ----------------
__global__ void k_zero(float* p, size_t n) {
    size_t i = (size_t)blockIdx.x * blockDim.x + threadIdx.x;
    if (i < n) p[i] = 0.f;
}
__global__ void k_copy(float* dst, const float* src, size_t n) {
    size_t i = (size_t)blockIdx.x * blockDim.x + threadIdx.x;
    if (i < n) dst[i] = src[i];
}

__global__ void k_gather_feats(const float* __restrict__ pooled, const int* __restrict__ vidx,
                               float* __restrict__ feats)
{
    int idx = blockIdx.x * blockDim.x + threadIdx.x;
    if (idx >= NVOBJ * (FF / 4)) return;
    int v = idx / (FF / 4), j = (idx - v * (FF / 4)) * 4;
    *reinterpret_cast<float4*>(feats + (size_t)v * FF + j) =
        *reinterpret_cast<const float4*>(pooled + (size_t)vidx[v] * FF + j);
}

__global__ void k_build_z(const float* __restrict__ facts, const float* __restrict__ q,
                          const float* __restrict__ m, float* __restrict__ z)
{
    size_t idx = (size_t)blockIdx.x * blockDim.x + threadIdx.x;
    if (idx >= (size_t)BSEQ * DD) return;
    int d = idx % DD;
    int i = idx / DD;
    int v = i / KK;
    float f = facts[idx];
    float qv = q[(size_t)v * DD + d];
    float mv = m[(size_t)v * DD + d];
    float* zr = z + (size_t)i * ZDIM;
    zr[d] = f * qv;
    zr[DD + d] = f * mv;
    zr[2 * DD + d] = fabsf(f - qv);
    zr[3 * DD + d] = fabsf(f - mv);
}

__global__ void k_score_softmax(const float* __restrict__ h1, const float* __restrict__ w2,
                                const float* __restrict__ w2b, float* __restrict__ gate)
{
    int v = blockIdx.x;
    int tid = threadIdx.x;
    int w = tid >> 5, lane = tid & 31;
    __shared__ float s[KK];
    const float* row = h1 + ((size_t)v * KK + w) * FF;
    float sum = 0.f;
    for (int j = lane; j < FF; j += 32) sum += row[j] * w2[j];
    #pragma unroll
    for (int o = 16; o > 0; o >>= 1) sum += __shfl_down_sync(0xffffffffu, sum, o);
    if (lane == 0) s[w] = sum + w2b[0];
    __syncthreads();
    if (tid == 0) {
        float mx = s[0];
        #pragma unroll
        for (int k = 1; k < KK; k++) mx = fmaxf(mx, s[k]);
        float tot = 0.f, e[KK];
        #pragma unroll
        for (int k = 0; k < KK; k++) { e[k] = expf(s[k] - mx); tot += e[k]; }
        #pragma unroll
        for (int k = 0; k < KK; k++) gate[v * KK + k] = e[k] / tot;
    }
}

__global__ void agru_pointwise4(const float* __restrict__ fW2, const float* __restrict__ hU2,
                                const float* __restrict__ gate, float* __restrict__ h, int t)
{
    int idx = blockIdx.x * blockDim.x + threadIdx.x;
    if (idx >= NVOBJ * D4) return;
    int v = idx / D4;
    int d = (idx - v * D4) * 4;
    int row = v * KK + t;
    float4 fr = *reinterpret_cast<const float4*>(fW2 + (size_t)row * D2 + d);
    float4 fh = *reinterpret_cast<const float4*>(fW2 + (size_t)row * D2 + DD + d);
    float4 ur = *reinterpret_cast<const float4*>(hU2 + (size_t)v * D2 + d);
    float4 uh = *reinterpret_cast<const float4*>(hU2 + (size_t)v * D2 + DD + d);
    float4 hv = *reinterpret_cast<float4*>(h + (size_t)v * DD + d);
    float gt = gate[row];
    float4 o;
    { float r = sigm(fr.x + ur.x); float ht = tanhf(fh.x + r * uh.x); o.x = gt * ht + (1.f - gt) * hv.x; }
    { float r = sigm(fr.y + ur.y); float ht = tanhf(fh.y + r * uh.y); o.y = gt * ht + (1.f - gt) * hv.y; }
    { float r = sigm(fr.z + ur.z); float ht = tanhf(fh.z + r * uh.z); o.z = gt * ht + (1.f - gt) * hv.z; }
    { float r = sigm(fr.w + ur.w); float ht = tanhf(fh.w + r * uh.w); o.w = gt * ht + (1.f - gt) * hv.w; }
    *reinterpret_cast<float4*>(h + (size_t)v * DD + d) = o;
}

__global__ void k_cat3(const float* __restrict__ m, const float* __restrict__ attn,
                       const float* __restrict__ q, float* __restrict__ cat)
{
    int idx = blockIdx.x * blockDim.x + threadIdx.x;
    if (idx >= NVOBJ * G3D) return;
    int v = idx / G3D, c = idx - v * G3D;
    float val;
    if (c < DD)           val = m[v * DD + c];
    else if (c < 2 * DD)  val = attn[v * DD + c - DD];
    else                  val = q[v * DD + c - 2 * DD];
    cat[idx] = val;
}

__global__ void k_cat2(const float* __restrict__ feats, const float* __restrict__ m,
                       float* __restrict__ cat)
{
    int idx = blockIdx.x * blockDim.x + threadIdx.x;
    if (idx >= NVOBJ * CAT2) return;
    int v = idx / CAT2, c = idx - v * CAT2;
    cat[idx] = (c < FF) ? feats[v * FF + c] : m[v * DD + (c - FF)];
}

__global__ void k_scatter(const float* __restrict__ upd, const int* __restrict__ vidx,
                          float* __restrict__ out)
{
    int idx = blockIdx.x * blockDim.x + threadIdx.x;
    if (idx >= NVOBJ * FF) return;
    int v = idx / FF, j = idx - v * FF;
    out[(size_t)vidx[v] * FF + j] = upd[idx];
}

// ---------------- host orchestration ----------------
static inline dim3 gemm_grid(int M, int N) {
    return dim3((N + 63) / 64, (M + 127) / 128);
}
#define EWG(n) ((int)(((n) + 255) / 256))

extern "C" void kernel_launch(void* const* d_in, const int* in_sizes, int n_in,
                              void* d_out, int out_size)
{
    const float* pooled  = (const float*)d_in[0];
    const float* concept = (const float*)d_in[1];
    const int*   seqlen  = (const int*)d_in[2];
    const int*   vidx    = (const int*)d_in[3];
    const float* Wih     = (const float*)d_in[4];
    const float* Whh     = (const float*)d_in[5];
    const float* bih     = (const float*)d_in[6];
    const float* bhh     = (const float*)d_in[7];
    const float* Wq_w    = (const float*)d_in[8];
    const float* Wq_b    = (const float*)d_in[9];
    const float* W1_w    = (const float*)d_in[10];
    const float* W1_b    = (const float*)d_in[11];
    const float* W2_w    = (const float*)d_in[12];
    const float* W2_b    = (const float*)d_in[13];
    const float* aWr     = (const float*)d_in[14];
    const float* aUr     = (const float*)d_in[15];
    const float* abr     = (const float*)d_in[16];
    const float* aWh     = (const float*)d_in[17];
    const float* aUh     = (const float*)d_in[18];
    const float* abh     = (const float*)d_in[19];
    const float* nmt_w   = (const float*)d_in[20];
    const float* nmt_b   = (const float*)d_in[21];
    const float* upd_w   = (const float*)d_in[22];
    const float* upd_b   = (const float*)d_in[23];
    float* out = (float*)d_out;

    float *xg, *xp, *hg, *h, *hb, *facts, *feats, *q, *m, *z, *h1, *gate;
    float *U2, *W2cat, *b2cat, *fW2, *hU2, *attn, *cat, *cat2, *upd;
    int *nact;
    cudaGetSymbolAddress((void**)&xg, g_xg);
    cudaGetSymbolAddress((void**)&xp, g_xp);
    cudaGetSymbolAddress((void**)&hg, g_hg);
    cudaGetSymbolAddress((void**)&h, g_h);
    cudaGetSymbolAddress((void**)&hb, g_hb);
    cudaGetSymbolAddress((void**)&facts, g_facts);
    cudaGetSymbolAddress((void**)&feats, g_feats);
    cudaGetSymbolAddress((void**)&q, g_q);
    cudaGetSymbolAddress((void**)&m, g_m);
    cudaGetSymbolAddress((void**)&z, g_z);
    cudaGetSymbolAddress((void**)&h1, g_h1);
    cudaGetSymbolAddress((void**)&gate, g_gate);
    cudaGetSymbolAddress((void**)&U2, g_U2);
    cudaGetSymbolAddress((void**)&W2cat, g_W2cat);
    cudaGetSymbolAddress((void**)&b2cat, g_b2cat);
    cudaGetSymbolAddress((void**)&fW2, g_fW2);
    cudaGetSymbolAddress((void**)&hU2, g_hU2);
    cudaGetSymbolAddress((void**)&attn, g_attn);
    cudaGetSymbolAddress((void**)&cat, g_cat);
    cudaGetSymbolAddress((void**)&cat2, g_cat2);
    cudaGetSymbolAddress((void**)&upd, g_upd);
    cudaGetSymbolAddress((void**)&nact, g_nact);

    // ===== length sort / packing metadata =====
    k_sort_init<<<1, 32>>>();
    k_hist<<<EWG(BSEQ), 256>>>(seqlen);
    k_base<<<1, 32>>>();
    k_perm<<<EWG(BSEQ), 256>>>(seqlen);

    // ===== bidirectional GRU fact embeddings (packed, time-major) =====
    for (int dir = 0; dir < 2; ++dir) {
        const float* Wih_d = Wih + (size_t)dir * G3D * DD;
        const float* Whh_d = Whh + (size_t)dir * G3D * DD;
        const float* bih_d = bih + dir * G3D;
        const float* bhh_d = bhh + dir * G3D;
        float* hdir = dir ? hb : h;

        k_pack_x<<<EWG((size_t)BLTOT * D4), 256>>>(concept, seqlen, xp, dir);
        // input projection on active rows only (per-t limit, rows t-major)
        gemm_nt_tc<<<gemm_grid(BLTOT, G3D), 256>>>(xp, Wih_d, bih_d, xg,
                                                   BLTOT, G3D, DD, 0, nact, 14);
        k_zero<<<EWG(BSEQ * DD), 256>>>(hdir, (size_t)BSEQ * DD);
        for (int t = 0; t < LL; ++t) {
            gemm_nt_tc<<<gemm_grid(BSEQ, G3D), 256>>>(hdir, Whh_d, bhh_d, hg,
                                                      BSEQ, G3D, DD, 0, nact + t, 30);
            gru_pointwise4<<<EWG(BSEQ * D4), 256>>>(xg, hg, hdir, t);
        }
    }
    k_unpack_facts<<<EWG(BSEQ * D4), 256>>>(h, hb, facts);

    // ===== query =====
    k_gather_feats<<<EWG(NVOBJ * (FF / 4)), 256>>>(pooled, vidx, feats);
    gemm_nt_tc<<<gemm_grid(NVOBJ, DD), 256>>>(feats, Wq_w, Wq_b, q,
                                              NVOBJ, DD, FF, 1, nullptr, 0);
    k_copy<<<EWG(NVOBJ * DD), 256>>>(m, q, (size_t)NVOBJ * DD);

    // ===== build fused AGRU weights [Wr;Wh], [Ur;Uh], [br;bh] =====
    k_copy<<<EWG(DD * DD), 256>>>(W2cat, aWr, (size_t)DD * DD);
    k_copy<<<EWG(DD * DD), 256>>>(W2cat + DD * DD, aWh, (size_t)DD * DD);
    k_copy<<<EWG(DD * DD), 256>>>(U2, aUr, (size_t)DD * DD);
    k_copy<<<EWG(DD * DD), 256>>>(U2 + DD * DD, aUh, (size_t)DD * DD);
    k_copy<<<EWG(DD), 256>>>(b2cat, abr, (size_t)DD);
    k_copy<<<EWG(DD), 256>>>(b2cat + DD, abh, (size_t)DD);

    gemm_nt_tc<<<gemm_grid(BSEQ, D2), 256>>>(facts, W2cat, b2cat, fW2,
                                             BSEQ, D2, DD, 0, nullptr, 0);

    // ===== episodic memory passes =====
    for (int it = 0; it < TM; ++it) {
        k_build_z<<<EWG((size_t)BSEQ * DD), 256>>>(facts, q, m, z);
        gemm_nt_tc<<<gemm_grid(BSEQ, FF), 256>>>(z, W1_w, W1_b, h1,
                                                 BSEQ, FF, ZDIM, 1, nullptr, 0);
        k_score_softmax<<<NVOBJ, 256>>>(h1, W2_w, W2_b, gate);
        k_zero<<<EWG(NVOBJ * DD), 256>>>(attn, (size_t)NVOBJ * DD);
        for (int t = 0; t < KK; ++t) {
            gemm_nt_tc<<<gemm_grid(NVOBJ, D2), 256>>>(attn, U2, nullptr, hU2,
                                                      NVOBJ, D2, DD, 0, nullptr, 0);
            agru_pointwise4<<<EWG(NVOBJ * D4), 256>>>(fW2, hU2, gate, attn, t);
        }
        k_cat3<<<EWG(NVOBJ * G3D), 256>>>(m, attn, q, cat);
        gemm_nt_tc<<<gemm_grid(NVOBJ, DD), 256>>>(cat, nmt_w, nmt_b, m,
                                                  NVOBJ, DD, G3D, 2, nullptr, 0);
    }

    // ===== object update + scatter into output =====
    k_cat2<<<EWG(NVOBJ * CAT2), 256>>>(feats, m, cat2);
    gemm_nt_tc<<<gemm_grid(NVOBJ, FF), 256>>>(cat2, upd_w, upd_b, upd,
                                              NVOBJ, FF, CAT2, 2, nullptr, 0);
    k_copy<<<EWG((size_t)NOBJ * FF), 256>>>(out, pooled, (size_t)NOBJ * FF);
    k_scatter<<<EWG(NVOBJ * FF), 256>>>(upd, vidx, out);
}